// round 5
// baseline (speedup 1.0000x reference)
#include <cuda_runtime.h>
#include <cstdint>

#define B_  32
#define T_  2048
#define D_  256
#define H_  256
#define G3_ 768

// Scratch (no cudaMalloc allowed): xg buffer [B,T,768] and layer-1 output [B,T,256]
__device__ float g_xg[(size_t)B_ * T_ * G3_];
__device__ float g_h1[(size_t)B_ * T_ * H_];

typedef unsigned long long u64t;

__device__ __forceinline__ u64t ffma2(u64t a, u64t b, u64t c) {
    u64t d;
    asm("fma.rn.f32x2 %0, %1, %2, %3;" : "=l"(d) : "l"(a), "l"(b), "l"(c));
    return d;
}
__device__ __forceinline__ u64t add2(u64t a, u64t b) {
    u64t d;
    asm("add.rn.f32x2 %0, %1, %2;" : "=l"(d) : "l"(a), "l"(b));
    return d;
}
__device__ __forceinline__ float hsum2(u64t v) {
    float lo, hi;
    asm("mov.b64 {%0, %1}, %2;" : "=f"(lo), "=f"(hi) : "l"(v));
    return lo + hi;
}
__device__ __forceinline__ float2 u2f2(u64t v) {
    float2 f;
    asm("mov.b64 {%0, %1}, %2;" : "=f"(f.x), "=f"(f.y) : "l"(v));
    return f;
}

// ---------------------------------------------------------------------------
// GEMM: out[m,n] = sum_k A[m,k] * W[n,k] + bias[n], via packed fma.rn.f32x2.
// A-tile stored DUPLICATED in smem ((a,a) adjacent) and W-tile TRANSPOSED so
// both FFMA2 operands come straight from LDS.128 with no pack instructions.
// Tiles: BM=128, BN=128, BK=16; 256 threads; 8(m) x 8(n as 4 pairs) micro-tile.
// ---------------------------------------------------------------------------
__global__ void __launch_bounds__(256)
gemm_xg_kernel(const float* __restrict__ A, const float* __restrict__ W,
               const float* __restrict__ bias, float* __restrict__ out)
{
    __shared__ float As_dup[16][260];   // [kk][2*m] = [kk][2*m+1] = A[m][kk]
    __shared__ float Wst[16][140];      // [kk][n]   = W[n][kk]
    const int tid = threadIdx.x;
    const int tx = tid & 15;   // n
    const int ty = tid >> 4;   // m
    const int bm = blockIdx.x * 128;
    const int bn = blockIdx.y * 128;

    u64t acc2[8][4];
    #pragma unroll
    for (int i = 0; i < 8; i++)
        #pragma unroll
        for (int u = 0; u < 4; u++) acc2[i][u] = 0ull;

    for (int kb = 0; kb < 256; kb += 16) {
        #pragma unroll
        for (int r = 0; r < 2; r++) {
            int idx = tid + r * 256;           // 512 float4 slots for 128x16 tile
            int row = idx >> 2;
            int c4  = (idx & 3) * 4;
            float4 v = *(const float4*)&A[(size_t)(bm + row) * 256 + kb + c4];
            *(float2*)&As_dup[c4 + 0][2 * row] = make_float2(v.x, v.x);
            *(float2*)&As_dup[c4 + 1][2 * row] = make_float2(v.y, v.y);
            *(float2*)&As_dup[c4 + 2][2 * row] = make_float2(v.z, v.z);
            *(float2*)&As_dup[c4 + 3][2 * row] = make_float2(v.w, v.w);
        }
        #pragma unroll
        for (int r = 0; r < 2; r++) {
            int idx = tid + r * 256;
            int row = idx >> 2;
            int c4  = (idx & 3) * 4;
            float4 v = *(const float4*)&W[(size_t)(bn + row) * 256 + kb + c4];
            Wst[c4 + 0][row] = v.x;
            Wst[c4 + 1][row] = v.y;
            Wst[c4 + 2][row] = v.z;
            Wst[c4 + 3][row] = v.w;
        }
        __syncthreads();
        #pragma unroll
        for (int kk = 0; kk < 16; kk++) {
            ulonglong2 a01 = *(const ulonglong2*)&As_dup[kk][ty * 16];
            ulonglong2 a23 = *(const ulonglong2*)&As_dup[kk][ty * 16 + 4];
            ulonglong2 a45 = *(const ulonglong2*)&As_dup[kk][ty * 16 + 8];
            ulonglong2 a67 = *(const ulonglong2*)&As_dup[kk][ty * 16 + 12];
            ulonglong2 b01 = *(const ulonglong2*)&Wst[kk][tx * 8];
            ulonglong2 b23 = *(const ulonglong2*)&Wst[kk][tx * 8 + 4];
            u64t aa[8] = {a01.x, a01.y, a23.x, a23.y, a45.x, a45.y, a67.x, a67.y};
            u64t bb[4] = {b01.x, b01.y, b23.x, b23.y};
            #pragma unroll
            for (int i = 0; i < 8; i++)
                #pragma unroll
                for (int u = 0; u < 4; u++)
                    acc2[i][u] = ffma2(aa[i], bb[u], acc2[i][u]);
        }
        __syncthreads();
    }

    const float4 b0 = *(const float4*)&bias[bn + tx * 8];
    const float4 b1 = *(const float4*)&bias[bn + tx * 8 + 4];
    #pragma unroll
    for (int i = 0; i < 8; i++) {
        float2 p0 = u2f2(acc2[i][0]);
        float2 p1 = u2f2(acc2[i][1]);
        float2 p2 = u2f2(acc2[i][2]);
        float2 p3 = u2f2(acc2[i][3]);
        float4 v0 = make_float4(p0.x + b0.x, p0.y + b0.y, p1.x + b0.z, p1.y + b0.w);
        float4 v1 = make_float4(p2.x + b1.x, p2.y + b1.y, p3.x + b1.z, p3.y + b1.w);
        size_t o = (size_t)(bm + ty * 8 + i) * G3_ + bn + tx * 8;
        *(float4*)&out[o]     = v0;
        *(float4*)&out[o + 4] = v1;
    }
}

// ---------------------------------------------------------------------------
// Recurrent kernel: cluster of 4 CTAs per batch element (grid = 128 CTAs).
// 256 threads = 64 hidden units x 4 K-slices. Each thread owns ALL THREE gate
// rows (r,z,n) of one hidden unit j (3 x 32 packed f32x2 pairs = 192 w-regs).
// After a 2-level quad shfl, lane s==0 holds (r,z,n) for unit j and computes
// the gate INLINE -> no hgc smem round-trip, no xgs staging, no extra syncs.
// ---------------------------------------------------------------------------
#define RTHREADS 256
#define HPAD 272   // 256 + 4-float pad per 64

__device__ __forceinline__ unsigned smem_u32(const void* p) {
    unsigned a;
    asm("{ .reg .u64 t; cvta.to.shared.u64 t, %1; cvt.u32.u64 %0, t; }"
        : "=r"(a) : "l"(p));
    return a;
}
__device__ __forceinline__ void st_cluster_f32(unsigned addr, unsigned rank, float v) {
    asm volatile(
        "{ .reg .b32 r; mapa.shared::cluster.u32 r, %0, %1; st.shared::cluster.f32 [r], %2; }"
        :: "r"(addr), "r"(rank), "f"(v) : "memory");
}
__device__ __forceinline__ void mbar_init(unsigned addr, unsigned count) {
    asm volatile("mbarrier.init.shared.b64 [%0], %1;" :: "r"(addr), "r"(count) : "memory");
}
__device__ __forceinline__ void mbar_arrive_peer(unsigned addr, unsigned rank) {
    asm volatile(
        "{ .reg .b32 r; mapa.shared::cluster.u32 r, %0, %1; "
        "mbarrier.arrive.release.cluster.shared::cluster.b64 _, [r]; }"
        :: "r"(addr), "r"(rank) : "memory");
}
__device__ __forceinline__ void mbar_wait_cluster(unsigned addr, unsigned parity) {
    asm volatile(
        "{\n\t.reg .pred P1;\n\t"
        "WAIT_%=:\n\t"
        "mbarrier.try_wait.parity.acquire.cluster.shared::cta.b64 P1, [%0], %1, 0x989680;\n\t"
        "@P1 bra DONE_%=;\n\t"
        "bra WAIT_%=;\n\t"
        "DONE_%=:\n\t}"
        :: "r"(addr), "r"(parity) : "memory");
}
__device__ __forceinline__ void cluster_barrier() {
    asm volatile("barrier.cluster.arrive.aligned;" ::: "memory");
    asm volatile("barrier.cluster.wait.aligned;"   ::: "memory");
}
__device__ __forceinline__ float fast_sigmoid(float x) {
    return 1.f / (1.f + __expf(-x));
}
__device__ __forceinline__ float fast_tanh(float x) {
    return 2.f / (1.f + __expf(-2.f * x)) - 1.f;   // saturates cleanly
}

// padded h layout: h[k] stored at k + (k>>6)*4; K-slice streams (s=0..3) are
// 272B apart -> distinct bank groups, conflict-free LDS.128 broadcasts.
__global__ void __cluster_dims__(4, 1, 1) __launch_bounds__(RTHREADS, 1)
gru_rec_kernel(const float* __restrict__ xg, const float* __restrict__ Whh,
               const float* __restrict__ bhh, float* __restrict__ out)
{
    const int tid = threadIdx.x;
    const int s   = tid & 3;    // K-slice (64 wide)
    const int j   = tid >> 2;   // hidden unit within chunk, 0..63
    const int b   = blockIdx.x >> 2;
    const int c   = blockIdx.x & 3;

    __shared__ __align__(16) float hb[2][HPAD];  // padded h, double buffered
    __shared__ __align__(8) unsigned long long mbar_s[2];

    // Weights: rows (g*256 + c*64 + j) for g=0..2, K range [s*64, s*64+64),
    // as 32 packed f32x2 pairs per gate row.
    u64t w2[3][32];
    #pragma unroll
    for (int g = 0; g < 3; g++) {
        const ulonglong2* wp =
            (const ulonglong2*)(Whh + (size_t)(g * 256 + c * 64 + j) * 256 + s * 64);
        #pragma unroll
        for (int k = 0; k < 16; k++) {
            ulonglong2 v = wp[k];
            w2[g][2 * k]     = v.x;
            w2[g][2 * k + 1] = v.y;
        }
    }

    const bool gate_lane = (s == 0);
    float b_r = 0.f, b_z = 0.f, b_n = 0.f;
    float xr = 0.f, xz = 0.f, xn = 0.f;     // prefetched xg for this step
    const float* xgb = xg + (size_t)b * T_ * G3_;
    const int jglob = c * 64 + j;
    if (gate_lane) {
        b_r = bhh[jglob];
        b_z = bhh[256 + jglob];
        b_n = bhh[512 + jglob];
        xr = xgb[jglob];
        xz = xgb[256 + jglob];
        xn = xgb[512 + jglob];
    }
    for (int i = tid; i < 2 * HPAD; i += RTHREADS)
        hb[0][i] = 0.f;                      // zero both buffers (h0 = 0)

    const unsigned mb0 = smem_u32(&mbar_s[0]);
    const unsigned mb1 = smem_u32(&mbar_s[1]);
    if (tid == 0) { mbar_init(mb0, 4); mbar_init(mb1, 4); }

    const int pidx = jglob + ((jglob >> 6) << 2);       // padded index (<HPAD)
    const unsigned addr0 = smem_u32(&hb[0][pidx]);
    const unsigned addr1 = smem_u32(&hb[1][pidx]);
    float hreg = 0.f;                                   // own h from last step
    __syncthreads();
    cluster_barrier();   // all mbarriers initialized before any remote arrive

    int ph0 = 0, ph1 = 0;
    int cur = 0;
    for (int t = 0; t < T_; t++) {
        // (1) wait for this step's h buffer to be fully delivered
        if (t) {
            unsigned wa = cur ? mb1 : mb0;
            int p = cur ? ph1 : ph0;
            mbar_wait_cluster(wa, p);
            if (cur) ph1 ^= 1; else ph0 ^= 1;
        }

        // (2) GEMV: 3 gate rows of unit j over this thread's 64-wide K slice
        const ulonglong2* h2 = (const ulonglong2*)hb[cur];
        u64t ar0 = 0, ar1 = 0, az0 = 0, az1 = 0, an0 = 0, an1 = 0;
        #pragma unroll
        for (int i = 0; i < 16; i++) {
            ulonglong2 hv = h2[s * 17 + i];
            ar0 = ffma2(w2[0][2 * i],     hv.x, ar0);
            ar1 = ffma2(w2[0][2 * i + 1], hv.y, ar1);
            az0 = ffma2(w2[1][2 * i],     hv.x, az0);
            az1 = ffma2(w2[1][2 * i + 1], hv.y, az1);
            an0 = ffma2(w2[2][2 * i],     hv.x, an0);
            an1 = ffma2(w2[2][2 * i + 1], hv.y, an1);
        }
        float hr = hsum2(add2(ar0, ar1));
        float hz = hsum2(add2(az0, az1));
        float hn = hsum2(add2(an0, an1));
        // (3) reduce across the 4 K-slices (quad lanes s=0..3)
        hr += __shfl_xor_sync(0xffffffffu, hr, 1);
        hr += __shfl_xor_sync(0xffffffffu, hr, 2);
        hz += __shfl_xor_sync(0xffffffffu, hz, 1);
        hz += __shfl_xor_sync(0xffffffffu, hz, 2);
        hn += __shfl_xor_sync(0xffffffffu, hn, 1);
        hn += __shfl_xor_sync(0xffffffffu, hn, 2);

        // (4) gates INLINE on lane s==0, broadcast, prefetch next xg
        if (gate_lane) {
            float xr_n = 0.f, xz_n = 0.f, xn_n = 0.f;
            if (t + 1 < T_) {
                const float* xgt = xgb + (size_t)(t + 1) * G3_;
                xr_n = xgt[jglob];
                xz_n = xgt[256 + jglob];
                xn_n = xgt[512 + jglob];
            }
            float r  = fast_sigmoid(xr + hr + b_r);
            float z  = fast_sigmoid(xz + hz + b_z);
            float nn = fast_tanh(xn + (hn + b_n) * r);
            float hnew = (1.f - z) * nn + z * hreg;
            hreg = hnew;
            unsigned dsta = cur ? addr0 : addr1;      // write buffer cur^1
            #pragma unroll
            for (int p = 0; p < 4; p++) st_cluster_f32(dsta, p, hnew);
            out[((size_t)b * T_ + t) * H_ + jglob] = hnew;
            xr = xr_n; xz = xz_n; xn = xn_n;
        }

        __syncthreads();   // all gate lanes' DSMEM stores issued
        if (tid < 4) {
            unsigned am = cur ? mb0 : mb1;            // mbar of buffer cur^1
            mbar_arrive_peer(am, (unsigned)tid);
        }
        cur ^= 1;
    }
    cluster_barrier();   // don't exit while peers' DSMEM stores are in flight
}

// ---------------------------------------------------------------------------
static void launch_rec(const float* xg, const float* Whh, const float* bhh,
                       float* out)
{
    cudaLaunchConfig_t cfg = {};
    cfg.gridDim  = dim3(B_ * 4, 1, 1);
    cfg.blockDim = dim3(RTHREADS, 1, 1);
    cfg.dynamicSmemBytes = 0;
    cfg.stream = 0;
    cudaLaunchAttribute attrs[1];
    attrs[0].id = cudaLaunchAttributeClusterDimension;
    attrs[0].val.clusterDim.x = 4;
    attrs[0].val.clusterDim.y = 1;
    attrs[0].val.clusterDim.z = 1;
    cfg.attrs = attrs;
    cfg.numAttrs = 1;
    cudaLaunchKernelEx(&cfg, gru_rec_kernel, xg, Whh, bhh, out);
}

extern "C" void kernel_launch(void* const* d_in, const int* in_sizes, int n_in,
                              void* d_out, int out_size)
{
    (void)in_sizes; (void)n_in; (void)out_size;
    const float* x   = (const float*)d_in[0];
    const float* Wih = (const float*)d_in[1];
    const float* Whh = (const float*)d_in[2];
    const float* bih = (const float*)d_in[3];
    const float* bhh = (const float*)d_in[4];
    float* out = (float*)d_out;

    float* xgp; cudaGetSymbolAddress((void**)&xgp, g_xg);
    float* h1p; cudaGetSymbolAddress((void**)&h1p, g_h1);

    const dim3 ggrid(B_ * T_ / 128, G3_ / 128);

    // Layer 0
    gemm_xg_kernel<<<ggrid, 256>>>(x, Wih, bih, xgp);
    launch_rec(xgp, Whh, bhh, h1p);
    // Layer 1
    gemm_xg_kernel<<<ggrid, 256>>>(h1p, Wih + (size_t)G3_ * D_, bih + G3_, xgp);
    launch_rec(xgp, Whh + (size_t)G3_ * H_, bhh + G3_, out);
}

// round 7
// speedup vs baseline: 1.3113x; 1.3113x over previous
#include <cuda_runtime.h>
#include <cuda_bf16.h>
#include <cstdint>

#define B_  32
#define T_  2048
#define D_  256
#define H_  256
#define G3_ 768

// Scratch (no cudaMalloc allowed): xg buffer [B,T,768] and layer-1 output [B,T,256]
__device__ float g_xg[(size_t)B_ * T_ * G3_];
__device__ float g_h1[(size_t)B_ * T_ * H_];

typedef unsigned long long u64t;

__device__ __forceinline__ unsigned smem_u32(const void* p) {
    unsigned a;
    asm("{ .reg .u64 t; cvta.to.shared.u64 t, %1; cvt.u32.u64 %0, t; }"
        : "=r"(a) : "l"(p));
    return a;
}

// ===========================================================================
// Tensor-core GEMM via baseline mma.sync (bf16, split hi/lo, 3-term):
//   out[m,n] = sum_k A[m,k]*W[n,k] + bias[n]
// A[M,256] fp32, W[768,256] fp32. CTA tile 128(m) x 64(n), K chunked by 64.
// A = Ah + Al (bf16 hi + bf16 residual), W likewise; D ~= AhWh + AhWl + AlWh
// accumulated in f32 (dropped AlWl term ~2^-18 relative).
// 8 warps = 4(m) x 2(n); warp tile 32x32 = 2 m16-frags x 4 n8-frags.
// ===========================================================================
#define GT 256
#define KP 72            // padded K columns (bf16) per chunk row
#define SM_AH 0                          // 128*72*2 = 18432
#define SM_AL 18432
#define SM_BH 36864                      // 64*72*2 = 9216
#define SM_BL 46080
#define SM_TOT 55296

__device__ __forceinline__ void mma_bf16(float& d0, float& d1, float& d2, float& d3,
                                         unsigned a0, unsigned a1, unsigned a2, unsigned a3,
                                         unsigned b0, unsigned b1) {
    asm volatile(
        "mma.sync.aligned.m16n8k16.row.col.f32.bf16.bf16.f32 "
        "{%0,%1,%2,%3}, {%4,%5,%6,%7}, {%8,%9}, {%0,%1,%2,%3};"
        : "+f"(d0), "+f"(d1), "+f"(d2), "+f"(d3)
        : "r"(a0), "r"(a1), "r"(a2), "r"(a3), "r"(b0), "r"(b1));
}

__global__ void __launch_bounds__(GT)
gemm_tc_kernel(const float* __restrict__ A, const float* __restrict__ W,
               const float* __restrict__ bias, float* __restrict__ out)
{
    extern __shared__ char smem[];
    __nv_bfloat16* Ah = (__nv_bfloat16*)(smem + SM_AH);
    __nv_bfloat16* Al = (__nv_bfloat16*)(smem + SM_AL);
    __nv_bfloat16* Bh = (__nv_bfloat16*)(smem + SM_BH);
    __nv_bfloat16* Bl = (__nv_bfloat16*)(smem + SM_BL);

    const int tid  = threadIdx.x;
    const int lane = tid & 31;
    const int w    = tid >> 5;
    const int wm   = w & 3;            // warp m index (0..3)
    const int wn   = w >> 2;           // warp n index (0..1)
    const int bm   = blockIdx.x * 128;
    const int bn   = blockIdx.y * 64;

    const int lr = lane >> 2;          // lane row within fragment (0..7)
    const int lc = (lane & 3) * 2;     // lane k-pair base (0,2,4,6)

    float d[2][4][4];
    #pragma unroll
    for (int mf = 0; mf < 2; mf++)
        #pragma unroll
        for (int nf = 0; nf < 4; nf++)
            #pragma unroll
            for (int e = 0; e < 4; e++) d[mf][nf][e] = 0.f;

    for (int kb = 0; kb < 4; kb++) {
        // ---- load + split-convert A chunk [128 x 64] ----
        #pragma unroll
        for (int i = 0; i < 8; i++) {
            int idx = tid + i * GT;            // 2048 float4 slots
            int row = idx >> 4;
            int c4  = (idx & 15) * 4;
            float4 v = *(const float4*)&A[(size_t)(bm + row) * 256 + kb * 64 + c4];
            __nv_bfloat162 h01 = __float22bfloat162_rn(make_float2(v.x, v.y));
            __nv_bfloat162 h23 = __float22bfloat162_rn(make_float2(v.z, v.w));
            float2 r01 = __bfloat1622float2(h01);
            float2 r23 = __bfloat1622float2(h23);
            __nv_bfloat162 l01 = __float22bfloat162_rn(make_float2(v.x - r01.x, v.y - r01.y));
            __nv_bfloat162 l23 = __float22bfloat162_rn(make_float2(v.z - r23.x, v.w - r23.y));
            *(__nv_bfloat162*)&Ah[row * KP + c4]     = h01;
            *(__nv_bfloat162*)&Ah[row * KP + c4 + 2] = h23;
            *(__nv_bfloat162*)&Al[row * KP + c4]     = l01;
            *(__nv_bfloat162*)&Al[row * KP + c4 + 2] = l23;
        }
        // ---- load + split-convert W chunk [64 x 64] ----
        #pragma unroll
        for (int i = 0; i < 4; i++) {
            int idx = tid + i * GT;            // 1024 float4 slots
            int row = idx >> 4;
            int c4  = (idx & 15) * 4;
            float4 v = *(const float4*)&W[(size_t)(bn + row) * 256 + kb * 64 + c4];
            __nv_bfloat162 h01 = __float22bfloat162_rn(make_float2(v.x, v.y));
            __nv_bfloat162 h23 = __float22bfloat162_rn(make_float2(v.z, v.w));
            float2 r01 = __bfloat1622float2(h01);
            float2 r23 = __bfloat1622float2(h23);
            __nv_bfloat162 l01 = __float22bfloat162_rn(make_float2(v.x - r01.x, v.y - r01.y));
            __nv_bfloat162 l23 = __float22bfloat162_rn(make_float2(v.z - r23.x, v.w - r23.y));
            *(__nv_bfloat162*)&Bh[row * KP + c4]     = h01;
            *(__nv_bfloat162*)&Bh[row * KP + c4 + 2] = h23;
            *(__nv_bfloat162*)&Bl[row * KP + c4]     = l01;
            *(__nv_bfloat162*)&Bl[row * KP + c4 + 2] = l23;
        }
        __syncthreads();

        // ---- 4 k16 steps over this 64-chunk ----
        #pragma unroll
        for (int k16 = 0; k16 < 4; k16++) {
            const int kk = k16 * 16;
            unsigned ah[2][4], al[2][4], bh[4][2], bl[4][2];
            #pragma unroll
            for (int mf = 0; mf < 2; mf++) {
                int r0 = wm * 32 + mf * 16 + lr;
                ah[mf][0] = *(const unsigned*)&Ah[r0 * KP + kk + lc];
                ah[mf][1] = *(const unsigned*)&Ah[(r0 + 8) * KP + kk + lc];
                ah[mf][2] = *(const unsigned*)&Ah[r0 * KP + kk + 8 + lc];
                ah[mf][3] = *(const unsigned*)&Ah[(r0 + 8) * KP + kk + 8 + lc];
                al[mf][0] = *(const unsigned*)&Al[r0 * KP + kk + lc];
                al[mf][1] = *(const unsigned*)&Al[(r0 + 8) * KP + kk + lc];
                al[mf][2] = *(const unsigned*)&Al[r0 * KP + kk + 8 + lc];
                al[mf][3] = *(const unsigned*)&Al[(r0 + 8) * KP + kk + 8 + lc];
            }
            #pragma unroll
            for (int nf = 0; nf < 4; nf++) {
                int n0 = wn * 32 + nf * 8 + lr;
                bh[nf][0] = *(const unsigned*)&Bh[n0 * KP + kk + lc];
                bh[nf][1] = *(const unsigned*)&Bh[n0 * KP + kk + 8 + lc];
                bl[nf][0] = *(const unsigned*)&Bl[n0 * KP + kk + lc];
                bl[nf][1] = *(const unsigned*)&Bl[n0 * KP + kk + 8 + lc];
            }
            #pragma unroll
            for (int mf = 0; mf < 2; mf++)
                #pragma unroll
                for (int nf = 0; nf < 4; nf++) {
                    float* dd = d[mf][nf];
                    mma_bf16(dd[0], dd[1], dd[2], dd[3],
                             ah[mf][0], ah[mf][1], ah[mf][2], ah[mf][3],
                             bh[nf][0], bh[nf][1]);
                    mma_bf16(dd[0], dd[1], dd[2], dd[3],
                             ah[mf][0], ah[mf][1], ah[mf][2], ah[mf][3],
                             bl[nf][0], bl[nf][1]);
                    mma_bf16(dd[0], dd[1], dd[2], dd[3],
                             al[mf][0], al[mf][1], al[mf][2], al[mf][3],
                             bh[nf][0], bh[nf][1]);
                }
        }
        __syncthreads();
    }

    // ---- epilogue: D fragment layout -> out + bias ----
    #pragma unroll
    for (int mf = 0; mf < 2; mf++) {
        int m = bm + wm * 32 + mf * 16 + lr;
        #pragma unroll
        for (int nf = 0; nf < 4; nf++) {
            int n = bn + wn * 32 + nf * 8 + lc;
            float2 bv = *(const float2*)&bias[n];
            float2 v0 = make_float2(d[mf][nf][0] + bv.x, d[mf][nf][1] + bv.y);
            float2 v1 = make_float2(d[mf][nf][2] + bv.x, d[mf][nf][3] + bv.y);
            *(float2*)&out[(size_t)m * G3_ + n]       = v0;
            *(float2*)&out[(size_t)(m + 8) * G3_ + n] = v1;
        }
    }
}

// ===========================================================================
// Recurrent kernel — EXACT R4 version (best known: 6607.7us config).
// Cluster of 4 CTAs per batch element; 384 threads; 2 rows x 64-K per thread.
// ===========================================================================
#define RTHREADS 384
#define HPAD 272   // 256 + 4-float pad per 64

__device__ __forceinline__ void st_cluster_f32(unsigned addr, unsigned rank, float v) {
    asm volatile(
        "{ .reg .b32 r; mapa.shared::cluster.u32 r, %0, %1; st.shared::cluster.f32 [r], %2; }"
        :: "r"(addr), "r"(rank), "f"(v) : "memory");
}
__device__ __forceinline__ void mbar_init(unsigned addr, unsigned count) {
    asm volatile("mbarrier.init.shared.b64 [%0], %1;" :: "r"(addr), "r"(count) : "memory");
}
__device__ __forceinline__ void mbar_arrive_peer(unsigned addr, unsigned rank) {
    asm volatile(
        "{ .reg .b32 r; mapa.shared::cluster.u32 r, %0, %1; "
        "mbarrier.arrive.release.cluster.shared::cluster.b64 _, [r]; }"
        :: "r"(addr), "r"(rank) : "memory");
}
__device__ __forceinline__ void mbar_wait_cluster(unsigned addr, unsigned parity) {
    asm volatile(
        "{\n\t.reg .pred P1;\n\t"
        "WAIT_%=:\n\t"
        "mbarrier.try_wait.parity.acquire.cluster.shared::cta.b64 P1, [%0], %1, 0x989680;\n\t"
        "@P1 bra DONE_%=;\n\t"
        "bra WAIT_%=;\n\t"
        "DONE_%=:\n\t}"
        :: "r"(addr), "r"(parity) : "memory");
}
__device__ __forceinline__ void cluster_barrier() {
    asm volatile("barrier.cluster.arrive.aligned;" ::: "memory");
    asm volatile("barrier.cluster.wait.aligned;"   ::: "memory");
}
__device__ __forceinline__ u64t ffma2(u64t a, u64t b, u64t c) {
    u64t d;
    asm("fma.rn.f32x2 %0, %1, %2, %3;" : "=l"(d) : "l"(a), "l"(b), "l"(c));
    return d;
}
__device__ __forceinline__ u64t add2(u64t a, u64t b) {
    u64t d;
    asm("add.rn.f32x2 %0, %1, %2;" : "=l"(d) : "l"(a), "l"(b));
    return d;
}
__device__ __forceinline__ float hsum2(u64t v) {
    float lo, hi;
    asm("mov.b64 {%0, %1}, %2;" : "=f"(lo), "=f"(hi) : "l"(v));
    return lo + hi;
}
__device__ __forceinline__ float fast_sigmoid(float x) {
    return 1.f / (1.f + __expf(-x));
}
__device__ __forceinline__ float fast_tanh(float x) {
    return 2.f / (1.f + __expf(-2.f * x)) - 1.f;   // saturates cleanly
}

__global__ void __cluster_dims__(4, 1, 1) __launch_bounds__(RTHREADS, 1)
gru_rec_kernel(const float* __restrict__ xg, const float* __restrict__ Whh,
               const float* __restrict__ bhh, float* __restrict__ out)
{
    const int tid = threadIdx.x;
    const int s   = tid & 3;    // K-slice (64 wide)
    const int rg  = tid >> 2;   // row group (2 rows), 0..95
    const int b   = blockIdx.x >> 2;
    const int c   = blockIdx.x & 3;

    __shared__ __align__(16) float hb[2][HPAD];  // padded h, double buffered
    __shared__ float hgc[192];                   // reduced Whh@h for this chunk
    __shared__ float xgs[192];                   // staged xg for this step
    __shared__ __align__(8) unsigned long long mbar_s[2];

    u64t w2[2][32];
    #pragma unroll
    for (int q = 0; q < 2; q++) {
        int lr = rg * 2 + q;
        int g  = lr >> 6;
        int jl = lr & 63;
        const ulonglong2* wp =
            (const ulonglong2*)(Whh + (size_t)(g * 256 + c * 64 + jl) * 256 + s * 64);
        #pragma unroll
        for (int k = 0; k < 16; k++) {
            ulonglong2 v = wp[k];
            w2[q][2 * k]     = v.x;
            w2[q][2 * k + 1] = v.y;
        }
    }

    float b_r = 0.f, b_z = 0.f, b_n = 0.f;
    if (tid < 64) {
        b_r = bhh[c * 64 + tid];
        b_z = bhh[256 + c * 64 + tid];
        b_n = bhh[512 + c * 64 + tid];
    }
    for (int i = tid; i < 2 * HPAD; i += RTHREADS)
        hb[0][i] = 0.f;

    const unsigned mb0 = smem_u32(&mbar_s[0]);
    const unsigned mb1 = smem_u32(&mbar_s[1]);
    if (tid == 0) { mbar_init(mb0, 4); mbar_init(mb1, 4); }

    const float* xgb = xg + (size_t)b * T_ * G3_;
    const int xoff = (tid >> 6) * 256 + c * 64 + (tid & 63);
    float xgc = (tid < 192) ? xgb[xoff] : 0.f;

    const int jglob = c * 64 + (tid & 63);
    const int pidx  = jglob + ((jglob >> 6) << 2);
    const unsigned addr0 = smem_u32(&hb[0][pidx]);
    const unsigned addr1 = smem_u32(&hb[1][pidx]);
    float hreg = 0.f;
    __syncthreads();
    cluster_barrier();

    int ph0 = 0, ph1 = 0;
    int cur = 0;
    for (int t = 0; t < T_; t++) {
        if (t) {
            unsigned wa = cur ? mb1 : mb0;
            int p = cur ? ph1 : ph0;
            mbar_wait_cluster(wa, p);
            if (cur) ph1 ^= 1; else ph0 ^= 1;
        }
        if (tid < 192) xgs[tid] = xgc;
        float xgn = 0.f;
        if (tid < 192 && t + 1 < T_)
            xgn = xgb[(size_t)(t + 1) * G3_ + xoff];

        const ulonglong2* h2 = (const ulonglong2*)hb[cur];
        u64t a00 = 0, a01 = 0, a10 = 0, a11 = 0;
        #pragma unroll
        for (int i = 0; i < 16; i++) {
            ulonglong2 hv = h2[s * 17 + i];
            a00 = ffma2(w2[0][2 * i],     hv.x, a00);
            a01 = ffma2(w2[0][2 * i + 1], hv.y, a01);
            a10 = ffma2(w2[1][2 * i],     hv.x, a10);
            a11 = ffma2(w2[1][2 * i + 1], hv.y, a11);
        }
        float acc0 = hsum2(add2(a00, a01));
        float acc1 = hsum2(add2(a10, a11));
        acc0 += __shfl_xor_sync(0xffffffffu, acc0, 1);
        acc0 += __shfl_xor_sync(0xffffffffu, acc0, 2);
        acc1 += __shfl_xor_sync(0xffffffffu, acc1, 1);
        acc1 += __shfl_xor_sync(0xffffffffu, acc1, 2);
        if (s == 0) { hgc[rg * 2] = acc0; hgc[rg * 2 + 1] = acc1; }
        __syncthreads();

        if (tid < 64) {
            float hr = hgc[tid]       + b_r;
            float hz = hgc[64 + tid]  + b_z;
            float hn = hgc[128 + tid] + b_n;
            float xr = xgs[tid], xz = xgs[64 + tid], xn = xgs[128 + tid];
            float r  = fast_sigmoid(xr + hr);
            float z  = fast_sigmoid(xz + hz);
            float nn = fast_tanh(xn + r * hn);
            float hnew = (1.f - z) * nn + z * hreg;
            hreg = hnew;
            unsigned dsta = cur ? addr0 : addr1;
            #pragma unroll
            for (int p = 0; p < 4; p++) st_cluster_f32(dsta, p, hnew);
            out[((size_t)b * T_ + t) * H_ + jglob] = hnew;
            asm volatile("bar.sync 3, 64;" ::: "memory");
            if (tid < 4) {
                unsigned am = cur ? mb0 : mb1;
                mbar_arrive_peer(am, (unsigned)tid);
            }
        }

        xgc = xgn;
        cur ^= 1;
    }
    cluster_barrier();
}

// ---------------------------------------------------------------------------
static void launch_rec(const float* xg, const float* Whh, const float* bhh,
                       float* out)
{
    cudaLaunchConfig_t cfg = {};
    cfg.gridDim  = dim3(B_ * 4, 1, 1);
    cfg.blockDim = dim3(RTHREADS, 1, 1);
    cfg.dynamicSmemBytes = 0;
    cfg.stream = 0;
    cudaLaunchAttribute attrs[1];
    attrs[0].id = cudaLaunchAttributeClusterDimension;
    attrs[0].val.clusterDim.x = 4;
    attrs[0].val.clusterDim.y = 1;
    attrs[0].val.clusterDim.z = 1;
    cfg.attrs = attrs;
    cfg.numAttrs = 1;
    cudaLaunchKernelEx(&cfg, gru_rec_kernel, xg, Whh, bhh, out);
}

extern "C" void kernel_launch(void* const* d_in, const int* in_sizes, int n_in,
                              void* d_out, int out_size)
{
    (void)in_sizes; (void)n_in; (void)out_size;
    const float* x   = (const float*)d_in[0];
    const float* Wih = (const float*)d_in[1];
    const float* Whh = (const float*)d_in[2];
    const float* bih = (const float*)d_in[3];
    const float* bhh = (const float*)d_in[4];
    float* out = (float*)d_out;

    float* xgp; cudaGetSymbolAddress((void**)&xgp, g_xg);
    float* h1p; cudaGetSymbolAddress((void**)&h1p, g_h1);

    cudaFuncSetAttribute(gemm_tc_kernel,
                         cudaFuncAttributeMaxDynamicSharedMemorySize, SM_TOT);

    const dim3 ggrid(B_ * T_ / 128, G3_ / 64);   // 512 x 12

    // Layer 0
    gemm_tc_kernel<<<ggrid, GT, SM_TOT>>>(x, Wih, bih, xgp);
    launch_rec(xgp, Whh, bhh, h1p);
    // Layer 1
    gemm_tc_kernel<<<ggrid, GT, SM_TOT>>>(h1p, Wih + (size_t)G3_ * D_, bih + G3_, xgp);
    launch_rec(xgp, Whh + (size_t)G3_ * H_, bhh + G3_, out);
}